// round 1
// baseline (speedup 1.0000x reference)
#include <cuda_runtime.h>
#include <math.h>

#define BATCH  64
#define TSTEPS 512
#define DIN    512
#define DH     1024

// ---------------- grid-wide barrier state ----------------
__device__ unsigned g_count;
__device__ unsigned g_gen;

__global__ void init_sync_kernel() { g_count = 0u; g_gen = 0u; }

// ---------------- Kernel A: C[b*T+t, :] = x @ W + bias ----------------
// X: [32768, 512] row-major, W: [512, 1024] row-major, C: [32768, 1024]
__global__ __launch_bounds__(256) void gemm_xw_kernel(
    const float* __restrict__ X, const float* __restrict__ W,
    const float* __restrict__ bias, float* __restrict__ C)
{
    __shared__ float As[16][64];   // [k][m]
    __shared__ float Bs[16][68];   // [k][n] (+pad)

    const int tid   = threadIdx.x;
    const int tx    = tid & 15;
    const int ty    = tid >> 4;
    const int mBase = blockIdx.y << 6;
    const int nBase = blockIdx.x << 6;

    const int lm = tid >> 2;          // 0..63   (A row)
    const int lk = (tid & 3) << 2;    // 0,4,8,12 (A k group)
    const int bk = tid >> 4;          // 0..15   (B k row)
    const int bn = (tid & 15) << 2;   // 0..60   (B n group)

    float acc[4][4] = {};

    for (int k0 = 0; k0 < DIN; k0 += 16) {
        float4 av = *(const float4*)(X + (size_t)(mBase + lm) * DIN + k0 + lk);
        float4 bv = *(const float4*)(W + (size_t)(k0 + bk) * DH + nBase + bn);
        As[lk + 0][lm] = av.x;
        As[lk + 1][lm] = av.y;
        As[lk + 2][lm] = av.z;
        As[lk + 3][lm] = av.w;
        *(float4*)&Bs[bk][bn] = bv;
        __syncthreads();
#pragma unroll
        for (int kk = 0; kk < 16; ++kk) {
            float4 a = *(const float4*)&As[kk][ty << 2];
            float4 b = *(const float4*)&Bs[kk][tx << 2];
            float ar[4] = {a.x, a.y, a.z, a.w};
            float br[4] = {b.x, b.y, b.z, b.w};
#pragma unroll
            for (int i = 0; i < 4; ++i)
#pragma unroll
                for (int j = 0; j < 4; ++j)
                    acc[i][j] += ar[i] * br[j];
        }
        __syncthreads();
    }

    float4 bb = *(const float4*)(bias + nBase + (tx << 2));
#pragma unroll
    for (int i = 0; i < 4; ++i) {
        float4 o;
        o.x = acc[i][0] + bb.x;
        o.y = acc[i][1] + bb.y;
        o.z = acc[i][2] + bb.z;
        o.w = acc[i][3] + bb.w;
        *(float4*)(C + (size_t)(mBase + (ty << 2) + i) * DH + nBase + (tx << 2)) = o;
    }
}

// ---------------- Kernel B: persistent recurrence ----------------
// For t = 0..511:  out[b,t,:] = tanh(out[b,t,:] + h_{t-1} @ R)
// h_{t-1} = h0 (t==0) else out[:, t-1, :]  (in-place: xW preact lives in out)
// Grid: 128 blocks = 2 (M tiles of 32) x 64 (N tiles of 16). 128 thr, 2x2 micro.
#define NB  128
#define TPB 128
#define KT  64

__global__ __launch_bounds__(TPB) void rnn_recur_kernel(
    const float* __restrict__ h0, const float* __restrict__ R, float* out)
{
    __shared__ float sH[2][32][KT + 4];  // [buf][batch-local][k]
    __shared__ float sR[2][16][KT + 4];  // [buf][j-local][k] (transposed R tile)

    const int tid   = threadIdx.x;
    const int gm    = blockIdx.x & 1;    // 0..1
    const int gn    = blockIdx.x >> 1;   // 0..63
    const int mBase = gm << 5;           // 0 / 32
    const int jBase = gn << 4;           // 0..1008
    const int tm    = tid & 15;          // micro M
    const int tn    = tid >> 4;          // micro N (0..7)

    for (int t = 0; t < TSTEPS; ++t) {
        const float* hb;
        size_t hstride;
        if (t == 0) { hb = h0;                              hstride = DH; }
        else        { hb = out + (size_t)(t - 1) * DH;      hstride = (size_t)TSTEPS * DH; }

        float acc00 = 0.f, acc01 = 0.f, acc10 = 0.f, acc11 = 0.f;

        float4 hreg[4];
        float  rreg[8];

        // ---- prefetch tile 0 into buf 0 ----
#pragma unroll
        for (int i = 0; i < 4; ++i) {
            int s = tid + i * TPB;
            int b = s >> 4;
            int kq = (s & 15) << 2;
            hreg[i] = __ldcg((const float4*)(hb + (size_t)(mBase + b) * hstride + kq));
        }
#pragma unroll
        for (int p = 0; p < 8; ++p) {
            int s = tid + p * TPB;
            int k = s >> 4;
            int j = s & 15;
            rreg[p] = __ldg(R + (size_t)k * DH + jBase + j);
        }
#pragma unroll
        for (int i = 0; i < 4; ++i) {
            int s = tid + i * TPB;
            *(float4*)&sH[0][s >> 4][(s & 15) << 2] = hreg[i];
        }
#pragma unroll
        for (int p = 0; p < 8; ++p) {
            int s = tid + p * TPB;
            sR[0][s & 15][s >> 4] = rreg[p];
        }

        int buf = 0;
#pragma unroll 1
        for (int it = 0; it < DH / KT; ++it) {
            __syncthreads();   // current buf fully written; other buf free
            const int ktn = (it + 1) * KT;
            const bool more = (it + 1 < DH / KT);
            if (more) {
#pragma unroll
                for (int i = 0; i < 4; ++i) {
                    int s = tid + i * TPB;
                    int b = s >> 4;
                    int kq = (s & 15) << 2;
                    hreg[i] = __ldcg((const float4*)(hb + (size_t)(mBase + b) * hstride + ktn + kq));
                }
#pragma unroll
                for (int p = 0; p < 8; ++p) {
                    int s = tid + p * TPB;
                    int k = s >> 4;
                    int j = s & 15;
                    rreg[p] = __ldg(R + (size_t)(ktn + k) * DH + jBase + j);
                }
            }
            // ---- compute from buf ----
#pragma unroll
            for (int k = 0; k < KT; k += 4) {
                float4 h0v = *(const float4*)&sH[buf][tm][k];
                float4 h1v = *(const float4*)&sH[buf][tm + 16][k];
                float4 r0v = *(const float4*)&sR[buf][tn][k];
                float4 r1v = *(const float4*)&sR[buf][tn + 8][k];
                acc00 += h0v.x * r0v.x + h0v.y * r0v.y + h0v.z * r0v.z + h0v.w * r0v.w;
                acc01 += h0v.x * r1v.x + h0v.y * r1v.y + h0v.z * r1v.z + h0v.w * r1v.w;
                acc10 += h1v.x * r0v.x + h1v.y * r0v.y + h1v.z * r0v.z + h1v.w * r0v.w;
                acc11 += h1v.x * r1v.x + h1v.y * r1v.y + h1v.z * r1v.z + h1v.w * r1v.w;
            }
            if (more) {
                int nb = buf ^ 1;
#pragma unroll
                for (int i = 0; i < 4; ++i) {
                    int s = tid + i * TPB;
                    *(float4*)&sH[nb][s >> 4][(s & 15) << 2] = hreg[i];
                }
#pragma unroll
                for (int p = 0; p < 8; ++p) {
                    int s = tid + p * TPB;
                    sR[nb][s & 15][s >> 4] = rreg[p];
                }
                buf = nb;
            }
        }

        // ---- epilogue: add preact, tanh, write h_t ----
        const int m0 = mBase + tm;
        const int m1 = m0 + 16;
        const int j0 = jBase + tn;
        const int j1 = j0 + 8;
        const size_t r0 = ((size_t)m0 * TSTEPS + t) * DH;
        const size_t r1 = ((size_t)m1 * TSTEPS + t) * DH;
        out[r0 + j0] = tanhf(out[r0 + j0] + acc00);
        out[r0 + j1] = tanhf(out[r0 + j1] + acc01);
        out[r1 + j0] = tanhf(out[r1 + j0] + acc10);
        out[r1 + j1] = tanhf(out[r1 + j1] + acc11);

        // ---- grid-wide barrier (release writes of step t) ----
        __syncthreads();
        if (tid == 0) {
            __threadfence();
            unsigned arrived = atomicAdd(&g_count, 1u);
            if (arrived == NB - 1) {
                g_count = 0u;
                __threadfence();
                *(volatile unsigned*)&g_gen = (unsigned)(t + 1);
            } else {
                while (*(volatile unsigned*)&g_gen != (unsigned)(t + 1)) { __nanosleep(32); }
                __threadfence();
            }
        }
        __syncthreads();
    }
}

// ---------------- launch ----------------
extern "C" void kernel_launch(void* const* d_in, const int* in_sizes, int n_in,
                              void* d_out, int out_size)
{
    const float* x  = (const float*)d_in[0];   // [64,512,512]
    const float* h0 = (const float*)d_in[1];   // [64,1024]
    const float* W  = (const float*)d_in[2];   // [512,1024]
    const float* R  = (const float*)d_in[3];   // [1024,1024]
    const float* b  = (const float*)d_in[4];   // [1,1024]
    float* out = (float*)d_out;                // [64,512,1024]

    init_sync_kernel<<<1, 1>>>();

    dim3 gridA(DH / 64, (BATCH * TSTEPS) / 64);  // (16, 512)
    gemm_xw_kernel<<<gridA, 256>>>(x, W, b, out);

    rnn_recur_kernel<<<NB, TPB>>>(h0, R, out);
}

// round 2
// speedup vs baseline: 1.4232x; 1.4232x over previous
#include <cuda_runtime.h>
#include <math.h>
#include <string.h>

#define BATCH  64
#define TSTEPS 512
#define DIN    512
#define DH     1024

typedef unsigned long long ull;

__device__ __forceinline__ ull pack2(float v) {
    ull r; asm("mov.b64 %0, {%1, %1};" : "=l"(r) : "f"(v)); return r;
}
__device__ __forceinline__ ull f2u(float2 v) {
    ull r; memcpy(&r, &v, 8); return r;
}
__device__ __forceinline__ float2 u2f(ull v) {
    float2 r; memcpy(&r, &v, 8); return r;
}
__device__ __forceinline__ void fma2(ull& acc, ull a, ull b) {
    asm("fma.rn.f32x2 %0, %1, %2, %0;" : "+l"(acc) : "l"(a), "l"(b));
}

// ---------------- grid-wide barrier state ----------------
__device__ unsigned g_count;
__device__ unsigned g_gen;

__global__ void init_sync_kernel() { g_count = 0u; g_gen = 0u; }

// ---------------- Kernel A: C = x @ W + bias  (f32x2 inner) ----------------
__global__ __launch_bounds__(256) void gemm_xw_kernel(
    const float* __restrict__ X, const float* __restrict__ W,
    const float* __restrict__ bias, float* __restrict__ C)
{
    __shared__ float As[16][64];   // [k][m]
    __shared__ float Bs[16][68];   // [k][n] (+pad)

    const int tid   = threadIdx.x;
    const int tx    = tid & 15;
    const int ty    = tid >> 4;
    const int mBase = blockIdx.y << 6;
    const int nBase = blockIdx.x << 6;

    const int lm = tid >> 2;
    const int lk = (tid & 3) << 2;
    const int bk = tid >> 4;
    const int bn = (tid & 15) << 2;

    ull acc2[4][2];
#pragma unroll
    for (int i = 0; i < 4; ++i) { acc2[i][0] = 0ull; acc2[i][1] = 0ull; }

    for (int k0 = 0; k0 < DIN; k0 += 16) {
        float4 av = *(const float4*)(X + (size_t)(mBase + lm) * DIN + k0 + lk);
        float4 bv = *(const float4*)(W + (size_t)(k0 + bk) * DH + nBase + bn);
        As[lk + 0][lm] = av.x;
        As[lk + 1][lm] = av.y;
        As[lk + 2][lm] = av.z;
        As[lk + 3][lm] = av.w;
        *(float4*)&Bs[bk][bn] = bv;
        __syncthreads();
#pragma unroll
        for (int kk = 0; kk < 16; ++kk) {
            float4 a = *(const float4*)&As[kk][ty << 2];
            float4 b = *(const float4*)&Bs[kk][tx << 2];
            ull b01 = f2u(make_float2(b.x, b.y));
            ull b23 = f2u(make_float2(b.z, b.w));
            ull aa0 = pack2(a.x), aa1 = pack2(a.y), aa2 = pack2(a.z), aa3 = pack2(a.w);
            fma2(acc2[0][0], aa0, b01); fma2(acc2[0][1], aa0, b23);
            fma2(acc2[1][0], aa1, b01); fma2(acc2[1][1], aa1, b23);
            fma2(acc2[2][0], aa2, b01); fma2(acc2[2][1], aa2, b23);
            fma2(acc2[3][0], aa3, b01); fma2(acc2[3][1], aa3, b23);
        }
        __syncthreads();
    }

    float4 bb = *(const float4*)(bias + nBase + (tx << 2));
#pragma unroll
    for (int i = 0; i < 4; ++i) {
        float2 c0 = u2f(acc2[i][0]);
        float2 c1 = u2f(acc2[i][1]);
        float4 o;
        o.x = c0.x + bb.x;
        o.y = c0.y + bb.y;
        o.z = c1.x + bb.z;
        o.w = c1.y + bb.w;
        *(float4*)(C + (size_t)(mBase + (ty << 2) + i) * DH + nBase + (tx << 2)) = o;
    }
}

// ---------------- Kernel B: persistent recurrence (f32x2, warp K-split) ----
// 128 blocks (2 M-groups x 64 N-groups), 512 threads = 16 warps.
// Warp w owns K range [w*64, w*64+64), double-buffered in 16-k chunks.
// Lane: mi = lane&7 (m = mi*4..+3), ji = lane>>3 (j = ji*4..+3).
// Accs: 8 x f32x2, pairing adjacent M rows.
#define NB   128
#define TPB  512

// smem float offsets
#define SH_OFF   0            // [w][buf][k(16)][m(32)]         : 16*2*512 = 16384
#define SR_OFF   16384        // [w][buf][k(16)][jdup(32, s36)] : 16*2*576 = 18432
#define SP_OFF   34816        // [oidx(512)][q(16), s17]        : 8704
#define SMEM_FLOATS (SP_OFF + 8704)

struct StageRegs { float4 h[4]; float4 r[2]; };

__device__ __forceinline__ void load_stage(
    StageRegs& sr, const float* hb, size_t hstr, int mBase, int jBase,
    const float* __restrict__ R, int k0, int lane)
{
#pragma unroll
    for (int i = 0; i < 4; ++i)
        sr.h[i] = __ldcg((const float4*)(hb + (size_t)(mBase + lane) * hstr + k0 + i * 4));
    const int kk = lane & 15;
    const int q  = lane >> 4;
    sr.r[0] = __ldg((const float4*)(R + (size_t)(k0 + kk) * DH + jBase + q * 4));
    sr.r[1] = __ldg((const float4*)(R + (size_t)(k0 + kk) * DH + jBase + (q + 2) * 4));
}

__device__ __forceinline__ void store_stage(
    const StageRegs& sr, float* S, int w, int buf, int lane)
{
    float* Hb = S + SH_OFF + w * 1024 + buf * 512;
#pragma unroll
    for (int i = 0; i < 4; ++i) {
        Hb[(i * 4 + 0) * 32 + lane] = sr.h[i].x;
        Hb[(i * 4 + 1) * 32 + lane] = sr.h[i].y;
        Hb[(i * 4 + 2) * 32 + lane] = sr.h[i].z;
        Hb[(i * 4 + 3) * 32 + lane] = sr.h[i].w;
    }
    float* Rb = S + SR_OFF + w * 1152 + buf * 576;
    const int kk = lane & 15;
    const int q  = lane >> 4;
#pragma unroll
    for (int rep = 0; rep < 2; ++rep) {
        float4 rv = sr.r[rep];
        int jq = q + 2 * rep;
        *(float4*)&Rb[kk * 36 + jq * 8]     = make_float4(rv.x, rv.x, rv.y, rv.y);
        *(float4*)&Rb[kk * 36 + jq * 8 + 4] = make_float4(rv.z, rv.z, rv.w, rv.w);
    }
}

__global__ __launch_bounds__(TPB, 1) void rnn_recur_kernel(
    const float* __restrict__ h0, const float* __restrict__ R, float* out)
{
    extern __shared__ float S[];

    const int tid   = threadIdx.x;
    const int w     = tid >> 5;
    const int lane  = tid & 31;
    const int mi    = lane & 7;
    const int ji    = lane >> 3;
    const int gm    = blockIdx.x & 1;
    const int gn    = blockIdx.x >> 1;
    const int mBase = gm << 5;           // 0 / 32
    const int jBase = gn << 4;           // 0..1008
    const int kw    = w << 6;            // warp K base

    // reader decode (epilogue)
    const int oidx  = tid;
    const int lr    = oidx & 31;
    const int s_r   = oidx >> 5;
    const int m_l   = (lr & 7) * 4 + ((s_r >> 1) & 1) * 2 + (s_r & 1);
    const int j_l   = (lr >> 3) * 4 + (s_r >> 2);

#pragma unroll 1
    for (int t = 0; t < TSTEPS; ++t) {
        const float* hb;
        size_t hstr;
        if (t == 0) { hb = h0;                         hstr = DH; }
        else        { hb = out + (size_t)(t - 1) * DH; hstr = (size_t)TSTEPS * DH; }

        ull acc[2][4];
#pragma unroll
        for (int p = 0; p < 2; ++p)
#pragma unroll
            for (int j = 0; j < 4; ++j) acc[p][j] = 0ull;

        StageRegs sr;
        load_stage(sr, hb, hstr, mBase, jBase, R, kw, lane);
        store_stage(sr, S, w, 0, lane);
        __syncwarp();

        int buf = 0;
#pragma unroll
        for (int it = 0; it < 4; ++it) {
            if (it < 3)
                load_stage(sr, hb, hstr, mBase, jBase, R, kw + (it + 1) * 16, lane);

            const float* Hb = S + SH_OFF + w * 1024 + buf * 512;
            const float* Rb = S + SR_OFF + w * 1152 + buf * 576;
#pragma unroll
            for (int k = 0; k < 16; ++k) {
                ull hh0 = f2u(*(const float2*)&Hb[k * 32 + mi * 4]);
                ull hh1 = f2u(*(const float2*)&Hb[k * 32 + mi * 4 + 2]);
                float4 ra = *(const float4*)&Rb[k * 36 + ji * 8];
                float4 rb = *(const float4*)&Rb[k * 36 + ji * 8 + 4];
                ull r0 = f2u(make_float2(ra.x, ra.y));
                ull r1 = f2u(make_float2(ra.z, ra.w));
                ull r2 = f2u(make_float2(rb.x, rb.y));
                ull r3 = f2u(make_float2(rb.z, rb.w));
                fma2(acc[0][0], hh0, r0); fma2(acc[1][0], hh1, r0);
                fma2(acc[0][1], hh0, r1); fma2(acc[1][1], hh1, r1);
                fma2(acc[0][2], hh0, r2); fma2(acc[1][2], hh1, r2);
                fma2(acc[0][3], hh0, r3); fma2(acc[1][3], hh1, r3);
            }

            if (it < 3)
                store_stage(sr, S, w, buf ^ 1, lane);
            __syncwarp();
            buf ^= 1;
        }

        // ---- write partials: SP[oidx][w], oidx = s*32 + lane (conflict-free) ----
        float* P = S + SP_OFF;
#pragma unroll
        for (int jj = 0; jj < 4; ++jj)
#pragma unroll
            for (int p = 0; p < 2; ++p) {
                float2 v = u2f(acc[p][jj]);
                int s0 = jj * 4 + p * 2;
                P[(s0 * 32 + lane) * 17 + w]       = v.x;
                P[((s0 + 1) * 32 + lane) * 17 + w] = v.y;
            }
        __syncthreads();

        // ---- reduce 16 partials + preact + tanh + store ----
        {
            const float* row = P + oidx * 17;
            float sum = 0.f;
#pragma unroll
            for (int q = 0; q < 16; ++q) sum += row[q];
            size_t oi = ((size_t)(mBase + m_l) * TSTEPS + t) * DH + jBase + j_l;
            float pre = __ldcg(out + oi);
            out[oi] = tanhf(pre + sum);
        }

        // ---- grid-wide barrier ----
        __syncthreads();
        if (tid == 0) {
            __threadfence();
            unsigned arrived = atomicAdd(&g_count, 1u);
            if (arrived == NB - 1) {
                g_count = 0u;
                __threadfence();
                *(volatile unsigned*)&g_gen = (unsigned)(t + 1);
            } else {
                while (*(volatile unsigned*)&g_gen != (unsigned)(t + 1)) { __nanosleep(32); }
                __threadfence();
            }
        }
        __syncthreads();
    }
}

// ---------------- launch ----------------
extern "C" void kernel_launch(void* const* d_in, const int* in_sizes, int n_in,
                              void* d_out, int out_size)
{
    const float* x  = (const float*)d_in[0];   // [64,512,512]
    const float* h0 = (const float*)d_in[1];   // [64,1024]
    const float* W  = (const float*)d_in[2];   // [512,1024]
    const float* R  = (const float*)d_in[3];   // [1024,1024]
    const float* b  = (const float*)d_in[4];   // [1,1024]
    float* out = (float*)d_out;                // [64,512,1024]

    const int smem_bytes = SMEM_FLOATS * 4;
    cudaFuncSetAttribute(rnn_recur_kernel,
                         cudaFuncAttributeMaxDynamicSharedMemorySize, smem_bytes);

    init_sync_kernel<<<1, 1>>>();

    dim3 gridA(DH / 64, (BATCH * TSTEPS) / 64);  // (16, 512)
    gemm_xw_kernel<<<gridA, 256>>>(x, W, b, out);

    rnn_recur_kernel<<<NB, TPB, smem_bytes>>>(h0, R, out);
}

// round 3
// speedup vs baseline: 2.4232x; 1.7026x over previous
#include <cuda_runtime.h>
#include <math.h>
#include <string.h>

#define BATCH  64
#define TSTEPS 512
#define DIN    512
#define DH     1024

typedef unsigned long long ull;

// ---------------- small helpers ----------------
__device__ __forceinline__ ull pack2(float v) {
    ull r; asm("mov.b64 %0, {%1, %1};" : "=l"(r) : "f"(v)); return r;
}
__device__ __forceinline__ ull f2u(float2 v) { ull r; memcpy(&r, &v, 8); return r; }
__device__ __forceinline__ float2 u2f(ull v) { float2 r; memcpy(&r, &v, 8); return r; }
__device__ __forceinline__ void fma2(ull& acc, ull a, ull b) {
    asm("fma.rn.f32x2 %0, %1, %2, %0;" : "+l"(acc) : "l"(a), "l"(b));
}
__device__ __forceinline__ unsigned s2u(const void* p) {
    unsigned a;
    asm("{ .reg .u64 t; cvta.to.shared.u64 t, %1; cvt.u32.u64 %0, t; }" : "=r"(a) : "l"(p));
    return a;
}
__device__ __forceinline__ void mbar_init(unsigned mb, unsigned cnt) {
    asm volatile("mbarrier.init.shared.b64 [%0], %1;" :: "r"(mb), "r"(cnt) : "memory");
}
__device__ __forceinline__ void mbar_expect_tx(unsigned mb, unsigned bytes) {
    asm volatile("mbarrier.arrive.expect_tx.shared.b64 _, [%0], %1;" :: "r"(mb), "r"(bytes) : "memory");
}
__device__ __forceinline__ void mbar_wait(unsigned mb, unsigned parity) {
    asm volatile(
        "{\n\t"
        ".reg .pred P;\n\t"
        "WAIT_%=:\n\t"
        "mbarrier.try_wait.parity.shared.b64 P, [%0], %1, 10000000;\n\t"
        "@P bra DONE_%=;\n\t"
        "bra WAIT_%=;\n\t"
        "DONE_%=:\n\t"
        "}"
        :: "r"(mb), "r"(parity) : "memory");
}
__device__ __forceinline__ void bulk_g2s(unsigned dst, const void* src, unsigned bytes, unsigned mb) {
    asm volatile(
        "cp.async.bulk.shared::cluster.global.mbarrier::complete_tx::bytes [%0], [%1], %2, [%3];"
        :: "r"(dst), "l"(src), "r"(bytes), "r"(mb) : "memory");
}

// ---------------- grid-wide barrier (monotonic, replay-safe) ----------------
__device__ ull g_count;   // zero-initialized at module load, never reset
__device__ ull g_gen;

// ---------------- Kernel A: C = x @ W + bias  (128x128 tile, f32x2) --------
__global__ __launch_bounds__(256) void gemm_xw_kernel(
    const float* __restrict__ X, const float* __restrict__ W,
    const float* __restrict__ bias, float* __restrict__ C)
{
    __shared__ float As[16][132];   // [k][m] transposed
    __shared__ float Bs[16][132];   // [k][n]

    const int tid   = threadIdx.x;
    const int tx    = tid & 15;
    const int ty    = tid >> 4;
    const int mBase = blockIdx.y << 7;
    const int nBase = blockIdx.x << 7;

    ull acc[4][8];
#pragma unroll
    for (int p = 0; p < 4; ++p)
#pragma unroll
        for (int n = 0; n < 8; ++n) acc[p][n] = 0ull;

    for (int k0 = 0; k0 < DIN; k0 += 16) {
        // stage A transposed: As[k][m]
#pragma unroll
        for (int p = 0; p < 2; ++p) {
            int idx = tid + p * 256;
            int m = idx >> 2, kq = (idx & 3) << 2;
            float4 v = *(const float4*)(X + (size_t)(mBase + m) * DIN + k0 + kq);
            As[kq + 0][m] = v.x;
            As[kq + 1][m] = v.y;
            As[kq + 2][m] = v.z;
            As[kq + 3][m] = v.w;
        }
        // stage B: Bs[k][n]
#pragma unroll
        for (int p = 0; p < 2; ++p) {
            int idx = tid + p * 256;
            int k = idx >> 5, nq = (idx & 31) << 2;
            *(float4*)&Bs[k][nq] = *(const float4*)(W + (size_t)(k0 + k) * DH + nBase + nq);
        }
        __syncthreads();
#pragma unroll
        for (int kk = 0; kk < 16; ++kk) {
            float4 a0 = *(const float4*)&As[kk][ty * 8];
            float4 a1 = *(const float4*)&As[kk][ty * 8 + 4];
            float4 b0 = *(const float4*)&Bs[kk][tx * 8];
            float4 b1 = *(const float4*)&Bs[kk][tx * 8 + 4];
            ull am[4];
            am[0] = f2u(make_float2(a0.x, a0.y));
            am[1] = f2u(make_float2(a0.z, a0.w));
            am[2] = f2u(make_float2(a1.x, a1.y));
            am[3] = f2u(make_float2(a1.z, a1.w));
            ull bn[8];
            bn[0] = pack2(b0.x); bn[1] = pack2(b0.y); bn[2] = pack2(b0.z); bn[3] = pack2(b0.w);
            bn[4] = pack2(b1.x); bn[5] = pack2(b1.y); bn[6] = pack2(b1.z); bn[7] = pack2(b1.w);
#pragma unroll
            for (int p = 0; p < 4; ++p)
#pragma unroll
                for (int n = 0; n < 8; ++n)
                    fma2(acc[p][n], am[p], bn[n]);
        }
        __syncthreads();
    }

    float4 bb0 = *(const float4*)(bias + nBase + tx * 8);
    float4 bb1 = *(const float4*)(bias + nBase + tx * 8 + 4);
    float bbs[8] = {bb0.x, bb0.y, bb0.z, bb0.w, bb1.x, bb1.y, bb1.z, bb1.w};

#pragma unroll
    for (int p = 0; p < 4; ++p) {
        float2 c[8];
#pragma unroll
        for (int n = 0; n < 8; ++n) c[n] = u2f(acc[p][n]);
        int row0 = mBase + ty * 8 + p * 2;
        float* out0 = C + (size_t)row0 * DH + nBase + tx * 8;
        float* out1 = out0 + DH;
        float4 o;
        o.x = c[0].x + bbs[0]; o.y = c[1].x + bbs[1]; o.z = c[2].x + bbs[2]; o.w = c[3].x + bbs[3];
        *(float4*)out0 = o;
        o.x = c[4].x + bbs[4]; o.y = c[5].x + bbs[5]; o.z = c[6].x + bbs[6]; o.w = c[7].x + bbs[7];
        *(float4*)(out0 + 4) = o;
        o.x = c[0].y + bbs[0]; o.y = c[1].y + bbs[1]; o.z = c[2].y + bbs[2]; o.w = c[3].y + bbs[3];
        *(float4*)out1 = o;
        o.x = c[4].y + bbs[4]; o.y = c[5].y + bbs[5]; o.z = c[6].y + bbs[6]; o.w = c[7].y + bbs[7];
        *(float4*)(out1 + 4) = o;
    }
}

// ---------------- Kernel B: persistent recurrence ----------------
// 128 blocks = 2 gm (m-tile 32) x 64 gn (j-tile 16). 512 threads = 16 warps.
// Warp w: jh = w&1 (j-half of 8), ks = w>>1 (k-range [ks*128, +128)).
// Lane: lm = lane>>2 (m rows {lm, lm+8, lm+16, lm+24}), lj = lane&3
//       (j = jh*8 + lj and jh*8 + lj + 4).
// h arrives via cp.async.bulk into smem [m][k] (row stride 1028 floats),
// 4 k-chunks of 256 floats with per-chunk mbarriers.
// R persistent in smem, transposed [j][k], row stride 1028.
// f32x2 accumulators pair over k; halves summed at epilogue.
#define NB  128
#define TPB 512
#define HSTRIDE 1028
#define H_OFF 0
#define R_OFF (32 * HSTRIDE)              // 32896
#define P_OFF (R_OFF + 16 * HSTRIDE)      // 49344
#define SMEM_FLOATS (P_OFF + 512 * 9)     // 53952 floats = 215808 B

__global__ __launch_bounds__(TPB, 1) void rnn_recur_kernel(
    const float* __restrict__ h0, const float* __restrict__ R, float* out)
{
    extern __shared__ float S[];
    __shared__ ull mbar[4];

    const int tid   = threadIdx.x;
    const int w     = tid >> 5;
    const int lane  = tid & 31;
    const int gm    = blockIdx.x & 1;
    const int gn    = blockIdx.x >> 1;
    const int mBase = gm << 5;
    const int jBase = gn << 4;
    const int jh    = w & 1;
    const int ks    = w >> 1;
    const int chunk = ks >> 1;

    const int lm = lane >> 2;
    const int lj = lane & 3;

    // ---- stage R transposed into smem (once) ----
#pragma unroll
    for (int p = 0; p < 8; ++p) {
        int idx = tid + p * TPB;          // 0..4095
        int k = idx >> 2, q = idx & 3;
        float4 v = *(const float4*)(R + (size_t)k * DH + jBase + q * 4);
        S[R_OFF + (q * 4 + 0) * HSTRIDE + k] = v.x;
        S[R_OFF + (q * 4 + 1) * HSTRIDE + k] = v.y;
        S[R_OFF + (q * 4 + 2) * HSTRIDE + k] = v.z;
        S[R_OFF + (q * 4 + 3) * HSTRIDE + k] = v.w;
    }
    if (tid == 0) {
#pragma unroll
        for (int c = 0; c < 4; ++c) mbar_init(s2u(&mbar[c]), 1u);
    }
    asm volatile("fence.proxy.async.shared::cta;" ::: "memory");
    __syncthreads();

    // per-lane smem row pointers
    const float* Hp0 = S + H_OFF + (size_t)(lm +  0) * HSTRIDE + ks * 128;
    const float* Hp1 = S + H_OFF + (size_t)(lm +  8) * HSTRIDE + ks * 128;
    const float* Hp2 = S + H_OFF + (size_t)(lm + 16) * HSTRIDE + ks * 128;
    const float* Hp3 = S + H_OFF + (size_t)(lm + 24) * HSTRIDE + ks * 128;
    const float* Rp0 = S + R_OFF + (size_t)(jh * 8 + lj) * HSTRIDE + ks * 128;
    const float* Rp1 = Rp0 + 4 * HSTRIDE;

    const unsigned mb_mine = s2u(&mbar[chunk]);

#pragma unroll 1
    for (int t = 0; t < TSTEPS; ++t) {
        // ---- issue h bulk copies: warp c copies k-chunk c (32 rows x 1KB) ----
        if (w < 4) {
            const unsigned mb = s2u(&mbar[w]);
            if (lane == 0) mbar_expect_tx(mb, 32768u);
            __syncwarp();
            const float* src;
            if (t == 0)
                src = h0 + (size_t)(mBase + lane) * DH + w * 256;
            else
                src = out + (size_t)(t - 1) * DH
                          + (size_t)(mBase + lane) * ((size_t)TSTEPS * DH) + w * 256;
            unsigned dst = s2u(S + H_OFF + (size_t)lane * HSTRIDE + w * 256);
            bulk_g2s(dst, src, 1024u, mb);
        }

        // ---- wait for my k-chunk ----
        mbar_wait(mb_mine, (unsigned)(t & 1));

        // ---- compute: acc pairs over k ----
        ull a00 = 0, a01 = 0, a10 = 0, a11 = 0, a20 = 0, a21 = 0, a30 = 0, a31 = 0;
#pragma unroll 16
        for (int kk = 0; kk < 64; ++kk) {
            const int off = kk * 2;
            ull ha = f2u(*(const float2*)(Hp0 + off));
            ull hb = f2u(*(const float2*)(Hp1 + off));
            ull hc = f2u(*(const float2*)(Hp2 + off));
            ull hd = f2u(*(const float2*)(Hp3 + off));
            ull r0 = f2u(*(const float2*)(Rp0 + off));
            ull r1 = f2u(*(const float2*)(Rp1 + off));
            fma2(a00, ha, r0); fma2(a01, ha, r1);
            fma2(a10, hb, r0); fma2(a11, hb, r1);
            fma2(a20, hc, r0); fma2(a21, hc, r1);
            fma2(a30, hd, r0); fma2(a31, hd, r1);
        }

        // ---- partials to smem ----
        {
            const int j0 = jh * 8 + lj;
            const int j1 = j0 + 4;
            float2 c;
            c = u2f(a00); S[P_OFF + ((lm +  0) * 16 + j0) * 9 + ks] = c.x + c.y;
            c = u2f(a01); S[P_OFF + ((lm +  0) * 16 + j1) * 9 + ks] = c.x + c.y;
            c = u2f(a10); S[P_OFF + ((lm +  8) * 16 + j0) * 9 + ks] = c.x + c.y;
            c = u2f(a11); S[P_OFF + ((lm +  8) * 16 + j1) * 9 + ks] = c.x + c.y;
            c = u2f(a20); S[P_OFF + ((lm + 16) * 16 + j0) * 9 + ks] = c.x + c.y;
            c = u2f(a21); S[P_OFF + ((lm + 16) * 16 + j1) * 9 + ks] = c.x + c.y;
            c = u2f(a30); S[P_OFF + ((lm + 24) * 16 + j0) * 9 + ks] = c.x + c.y;
            c = u2f(a31); S[P_OFF + ((lm + 24) * 16 + j1) * 9 + ks] = c.x + c.y;
        }
        __syncthreads();

        // ---- reduce 8 partials + preact + tanh + store ----
        {
            const int m_l = tid >> 4, j_l = tid & 15;
            const float* row = S + P_OFF + tid * 9;
            float sum = ((row[0] + row[1]) + (row[2] + row[3]))
                      + ((row[4] + row[5]) + (row[6] + row[7]));
            size_t oi = ((size_t)(mBase + m_l) * TSTEPS + t) * DH + jBase + j_l;
            float pre = __ldcg(out + oi);
            out[oi] = tanhf(pre + sum);
        }

        // ---- grid-wide barrier (monotonic generation) ----
        __threadfence();
        __syncthreads();
        if (tid == 0) {
            ull old = atomicAdd(&g_count, 1ull);
            ull target = old / NB + 1ull;
            if ((old % NB) == (ull)(NB - 1)) {
                *(volatile ull*)&g_gen = target;
            } else {
                while (*(volatile ull*)&g_gen < target) { __nanosleep(32); }
            }
        }
        __syncthreads();
    }
}

// ---------------- launch ----------------
extern "C" void kernel_launch(void* const* d_in, const int* in_sizes, int n_in,
                              void* d_out, int out_size)
{
    const float* x  = (const float*)d_in[0];   // [64,512,512]
    const float* h0 = (const float*)d_in[1];   // [64,1024]
    const float* W  = (const float*)d_in[2];   // [512,1024]
    const float* R  = (const float*)d_in[3];   // [1024,1024]
    const float* b  = (const float*)d_in[4];   // [1,1024]
    float* out = (float*)d_out;                // [64,512,1024]

    const int smem_bytes = SMEM_FLOATS * 4;
    cudaFuncSetAttribute(rnn_recur_kernel,
                         cudaFuncAttributeMaxDynamicSharedMemorySize, smem_bytes);

    dim3 gridA(DH / 128, (BATCH * TSTEPS) / 128);  // (8, 256)
    gemm_xw_kernel<<<gridA, 256>>>(x, W, b, out);

    rnn_recur_kernel<<<NB, TPB, smem_bytes>>>(h0, R, out);
}

// round 4
// speedup vs baseline: 2.6575x; 1.0967x over previous
#include <cuda_runtime.h>
#include <math.h>
#include <string.h>

#define BATCH  64
#define TSTEPS 512
#define DIN    512
#define DH     1024

typedef unsigned long long ull;

// ---------------- small helpers ----------------
__device__ __forceinline__ ull pack2(float v) {
    ull r; asm("mov.b64 %0, {%1, %1};" : "=l"(r) : "f"(v)); return r;
}
__device__ __forceinline__ ull f2u(float2 v) { ull r; memcpy(&r, &v, 8); return r; }
__device__ __forceinline__ float2 u2f(ull v) { float2 r; memcpy(&r, &v, 8); return r; }
__device__ __forceinline__ void fma2(ull& acc, ull a, ull b) {
    asm("fma.rn.f32x2 %0, %1, %2, %0;" : "+l"(acc) : "l"(a), "l"(b));
}
__device__ __forceinline__ unsigned s2u(const void* p) {
    unsigned a;
    asm("{ .reg .u64 t; cvta.to.shared.u64 t, %1; cvt.u32.u64 %0, t; }" : "=r"(a) : "l"(p));
    return a;
}
__device__ __forceinline__ void mbar_init(unsigned mb, unsigned cnt) {
    asm volatile("mbarrier.init.shared.b64 [%0], %1;" :: "r"(mb), "r"(cnt) : "memory");
}
__device__ __forceinline__ void mbar_expect_tx(unsigned mb, unsigned bytes) {
    asm volatile("mbarrier.arrive.expect_tx.shared.b64 _, [%0], %1;" :: "r"(mb), "r"(bytes) : "memory");
}
__device__ __forceinline__ void mbar_wait(unsigned mb, unsigned parity) {
    asm volatile(
        "{\n\t"
        ".reg .pred P;\n\t"
        "WAIT_%=:\n\t"
        "mbarrier.try_wait.parity.shared.b64 P, [%0], %1, 10000000;\n\t"
        "@P bra DONE_%=;\n\t"
        "bra WAIT_%=;\n\t"
        "DONE_%=:\n\t"
        "}"
        :: "r"(mb), "r"(parity) : "memory");
}
__device__ __forceinline__ void bulk_g2s(unsigned dst, const void* src, unsigned bytes, unsigned mb) {
    asm volatile(
        "cp.async.bulk.shared::cluster.global.mbarrier::complete_tx::bytes [%0], [%1], %2, [%3];"
        :: "r"(dst), "l"(src), "r"(bytes), "r"(mb) : "memory");
}

// ---------------- grid-wide barrier (monotonic, replay-safe) ----------------
__device__ ull g_count;
__device__ ull g_gen;

// ---------------- Kernel A: C = x @ W + bias  (128x128 tile, f32x2) --------
__global__ __launch_bounds__(256) void gemm_xw_kernel(
    const float* __restrict__ X, const float* __restrict__ W,
    const float* __restrict__ bias, float* __restrict__ C)
{
    __shared__ float As[16][132];   // [k][m]
    __shared__ float Bs[16][132];   // [k][n]

    const int tid   = threadIdx.x;
    const int tx    = tid & 15;
    const int ty    = tid >> 4;
    const int mBase = blockIdx.y << 7;
    const int nBase = blockIdx.x << 7;

    ull acc[4][8];
#pragma unroll
    for (int p = 0; p < 4; ++p)
#pragma unroll
        for (int n = 0; n < 8; ++n) acc[p][n] = 0ull;

    for (int k0 = 0; k0 < DIN; k0 += 16) {
#pragma unroll
        for (int p = 0; p < 2; ++p) {
            int idx = tid + p * 256;
            int m = idx >> 2, kq = (idx & 3) << 2;
            float4 v = *(const float4*)(X + (size_t)(mBase + m) * DIN + k0 + kq);
            As[kq + 0][m] = v.x;
            As[kq + 1][m] = v.y;
            As[kq + 2][m] = v.z;
            As[kq + 3][m] = v.w;
        }
#pragma unroll
        for (int p = 0; p < 2; ++p) {
            int idx = tid + p * 256;
            int k = idx >> 5, nq = (idx & 31) << 2;
            *(float4*)&Bs[k][nq] = *(const float4*)(W + (size_t)(k0 + k) * DH + nBase + nq);
        }
        __syncthreads();
#pragma unroll
        for (int kk = 0; kk < 16; ++kk) {
            float4 a0 = *(const float4*)&As[kk][ty * 8];
            float4 a1 = *(const float4*)&As[kk][ty * 8 + 4];
            float4 b0 = *(const float4*)&Bs[kk][tx * 8];
            float4 b1 = *(const float4*)&Bs[kk][tx * 8 + 4];
            ull am[4];
            am[0] = f2u(make_float2(a0.x, a0.y));
            am[1] = f2u(make_float2(a0.z, a0.w));
            am[2] = f2u(make_float2(a1.x, a1.y));
            am[3] = f2u(make_float2(a1.z, a1.w));
            ull bn[8];
            bn[0] = pack2(b0.x); bn[1] = pack2(b0.y); bn[2] = pack2(b0.z); bn[3] = pack2(b0.w);
            bn[4] = pack2(b1.x); bn[5] = pack2(b1.y); bn[6] = pack2(b1.z); bn[7] = pack2(b1.w);
#pragma unroll
            for (int p = 0; p < 4; ++p)
#pragma unroll
                for (int n = 0; n < 8; ++n)
                    fma2(acc[p][n], am[p], bn[n]);
        }
        __syncthreads();
    }

    float4 bb0 = *(const float4*)(bias + nBase + tx * 8);
    float4 bb1 = *(const float4*)(bias + nBase + tx * 8 + 4);
    float bbs[8] = {bb0.x, bb0.y, bb0.z, bb0.w, bb1.x, bb1.y, bb1.z, bb1.w};

#pragma unroll
    for (int p = 0; p < 4; ++p) {
        float2 c[8];
#pragma unroll
        for (int n = 0; n < 8; ++n) c[n] = u2f(acc[p][n]);
        int row0 = mBase + ty * 8 + p * 2;
        float* out0 = C + (size_t)row0 * DH + nBase + tx * 8;
        float* out1 = out0 + DH;
        float4 o;
        o.x = c[0].x + bbs[0]; o.y = c[1].x + bbs[1]; o.z = c[2].x + bbs[2]; o.w = c[3].x + bbs[3];
        *(float4*)out0 = o;
        o.x = c[4].x + bbs[4]; o.y = c[5].x + bbs[5]; o.z = c[6].x + bbs[6]; o.w = c[7].x + bbs[7];
        *(float4*)(out0 + 4) = o;
        o.x = c[0].y + bbs[0]; o.y = c[1].y + bbs[1]; o.z = c[2].y + bbs[2]; o.w = c[3].y + bbs[3];
        *(float4*)out1 = o;
        o.x = c[4].y + bbs[4]; o.y = c[5].y + bbs[5]; o.z = c[6].y + bbs[6]; o.w = c[7].y + bbs[7];
        *(float4*)(out1 + 4) = o;
    }
}

// ---------------- Kernel B: persistent recurrence (broadcast tiles) --------
// 128 blocks = 2 gm (m-tile 32) x 64 gn (j-tile 16). 512 threads = 16 warps.
// Warp w owns k-range [w*64, w*64+64). Lane = m_lane(0..7) x j_lane(0..3).
// Per-thread micro-tile: m rows {m_lane+8i}, j cols {j_lane+4i}, 4x4.
// h loads broadcast over j_lanes (8 distinct addrs), R loads broadcast over
// m_lanes (4 distinct addrs) -> 1.5 bank-bytes per fma2.
// Partials region ALIASES the H region (H dead after compute each step).
#define NB  128
#define TPB 512
#define HSTRIDE 1028
#define H_OFF 0
#define R_OFF (32 * HSTRIDE)                 // 32896
#define P_OFF 0                              // aliases H
#define SMEM_FLOATS (R_OFF + 16 * HSTRIDE)   // 49344 floats = 197376 B

__global__ __launch_bounds__(TPB, 1) void rnn_recur_kernel(
    const float* __restrict__ h0, const float* __restrict__ R, float* out)
{
    extern __shared__ float S[];
    __shared__ ull mbar[4];

    const int tid    = threadIdx.x;
    const int w      = tid >> 5;
    const int lane   = tid & 31;
    const int m_lane = lane & 7;
    const int j_lane = lane >> 3;
    const int gm     = blockIdx.x & 1;
    const int gn     = blockIdx.x >> 1;
    const int mBase  = gm << 5;
    const int jBase  = gn << 4;
    const int chunk  = w >> 2;               // k-chunk this warp waits on

    // ---- stage R transposed into smem [j][k] (once) ----
#pragma unroll
    for (int p = 0; p < 8; ++p) {
        int idx = tid + p * TPB;              // 0..4095
        int k = idx >> 2, q = idx & 3;
        float4 v = *(const float4*)(R + (size_t)k * DH + jBase + q * 4);
        S[R_OFF + (q * 4 + 0) * HSTRIDE + k] = v.x;
        S[R_OFF + (q * 4 + 1) * HSTRIDE + k] = v.y;
        S[R_OFF + (q * 4 + 2) * HSTRIDE + k] = v.z;
        S[R_OFF + (q * 4 + 3) * HSTRIDE + k] = v.w;
    }
    if (tid == 0) {
#pragma unroll
        for (int c = 0; c < 4; ++c) mbar_init(s2u(&mbar[c]), 1u);
    }
    asm volatile("fence.proxy.async.shared::cta;" ::: "memory");
    __syncthreads();

    // per-lane smem base pointers (k offset = warp's range)
    const float* Hp = S + H_OFF + (size_t)m_lane * HSTRIDE + w * 64;
    const float* Rp = S + R_OFF + (size_t)j_lane * HSTRIDE + w * 64;
    const unsigned mb_mine = s2u(&mbar[chunk]);

#pragma unroll 1
    for (int t = 0; t < TSTEPS; ++t) {
        // ---- issue h bulk copies: warp c copies k-chunk c (32 rows x 1KB) ----
        if (w < 4) {
            const unsigned mb = s2u(&mbar[w]);
            if (lane == 0) mbar_expect_tx(mb, 32768u);
            __syncwarp();
            const float* src;
            if (t == 0)
                src = h0 + (size_t)(mBase + lane) * DH + w * 256;
            else
                src = out + (size_t)(t - 1) * DH
                          + (size_t)(mBase + lane) * ((size_t)TSTEPS * DH) + w * 256;
            unsigned dst = s2u(S + H_OFF + (size_t)lane * HSTRIDE + w * 256);
            bulk_g2s(dst, src, 1024u, mb);
        }

        // ---- wait for my k-chunk ----
        mbar_wait(mb_mine, (unsigned)(t & 1));

        // ---- compute: 4x4 micro-tile, f32x2 pairs over k ----
        ull acc[4][4];
#pragma unroll
        for (int mi = 0; mi < 4; ++mi)
#pragma unroll
            for (int ji = 0; ji < 4; ++ji) acc[mi][ji] = 0ull;

#pragma unroll 4
        for (int it = 0; it < 16; ++it) {
            const int off = it * 4;           // 4 floats = 2 k-pairs
            float4 h[4], r[4];
#pragma unroll
            for (int mi = 0; mi < 4; ++mi)
                h[mi] = *(const float4*)(Hp + (size_t)(mi * 8) * HSTRIDE + off);
#pragma unroll
            for (int ji = 0; ji < 4; ++ji)
                r[ji] = *(const float4*)(Rp + (size_t)(ji * 4) * HSTRIDE + off);
#pragma unroll
            for (int mi = 0; mi < 4; ++mi) {
                ull hlo = f2u(make_float2(h[mi].x, h[mi].y));
                ull hhi = f2u(make_float2(h[mi].z, h[mi].w));
#pragma unroll
                for (int ji = 0; ji < 4; ++ji) {
                    fma2(acc[mi][ji], hlo, f2u(make_float2(r[ji].x, r[ji].y)));
                    fma2(acc[mi][ji], hhi, f2u(make_float2(r[ji].z, r[ji].w)));
                }
            }
        }

        // ---- all warps done reading H before P overwrites it ----
        __syncthreads();

        // ---- partials to smem (P aliases H): P[(m*16+j)*17 + w] ----
#pragma unroll
        for (int mi = 0; mi < 4; ++mi)
#pragma unroll
            for (int ji = 0; ji < 4; ++ji) {
                float2 c = u2f(acc[mi][ji]);
                int m_loc = m_lane + 8 * mi;
                int j_loc = j_lane + 4 * ji;
                S[P_OFF + (m_loc * 16 + j_loc) * 17 + w] = c.x + c.y;
            }
        __syncthreads();

        // ---- reduce 16 partials + preact + tanh + store ----
        {
            const int m_l = tid >> 4, j_l = tid & 15;
            const float* row = S + P_OFF + tid * 17;
            float s0 = 0.f, s1 = 0.f;
#pragma unroll
            for (int q = 0; q < 8; ++q) { s0 += row[q]; s1 += row[q + 8]; }
            size_t oi = ((size_t)(mBase + m_l) * TSTEPS + t) * DH + jBase + j_l;
            float pre = __ldcg(out + oi);
            out[oi] = tanhf(pre + s0 + s1);
        }

        // ---- grid-wide barrier (monotonic generation) ----
        __threadfence();
        __syncthreads();
        if (tid == 0) {
            ull old = atomicAdd(&g_count, 1ull);
            ull target = old / NB + 1ull;
            if ((old % NB) == (ull)(NB - 1)) {
                *(volatile ull*)&g_gen = target;
            } else {
                while (*(volatile ull*)&g_gen < target) { __nanosleep(32); }
            }
        }
        __syncthreads();
        // generic P writes -> async-proxy H writes (same addresses) ordering
        asm volatile("fence.proxy.async.shared::cta;" ::: "memory");
    }
}

// ---------------- launch ----------------
extern "C" void kernel_launch(void* const* d_in, const int* in_sizes, int n_in,
                              void* d_out, int out_size)
{
    const float* x  = (const float*)d_in[0];   // [64,512,512]
    const float* h0 = (const float*)d_in[1];   // [64,1024]
    const float* W  = (const float*)d_in[2];   // [512,1024]
    const float* R  = (const float*)d_in[3];   // [1024,1024]
    const float* b  = (const float*)d_in[4];   // [1,1024]
    float* out = (float*)d_out;                // [64,512,1024]

    const int smem_bytes = SMEM_FLOATS * 4;
    cudaFuncSetAttribute(rnn_recur_kernel,
                         cudaFuncAttributeMaxDynamicSharedMemorySize, smem_bytes);

    dim3 gridA(DH / 128, (BATCH * TSTEPS) / 128);  // (8, 256)
    gemm_xw_kernel<<<gridA, 256>>>(x, W, b, out);

    rnn_recur_kernel<<<NB, TPB, smem_bytes>>>(h0, R, out);
}